// round 9
// baseline (speedup 1.0000x reference)
#include <cuda_runtime.h>
#include <math.h>
#include <stdint.h>

#define DIM 4096
#define BSZ 1024
#define NW  12
#define BK  32                 // fp32 elems per tile row = 128B
#define NS  (DIM / BK)
#define TS  (128 * 128)        // bytes per 128x32 fp32 tile
#define G1S (3 * TS)           // gemm1 stage: Ur, Ui, X
#define G2S (4 * TS)           // gemm2 stage: Br, Bi, Sr, Si

// ---------------- device-global scratch ----------------
__device__ __align__(16) float g_sr[(size_t)BSZ * DIM];   // state re [b][k] (permuted)
__device__ __align__(16) float g_si[(size_t)BSZ * DIM];   // state im
__device__ int   g_invperm[DIM];
__device__ float g_norm[BSZ];

// ---------------- helpers ----------------
__device__ __forceinline__ void cvtf(uint32_t& r) {           // fp32 bits -> tf32(rna) bits
    asm("cvt.rna.tf32.f32 %0, %1;" : "+r"(r) : "f"(__uint_as_float(r)));
}
__device__ __forceinline__ uint32_t addcvt(uint32_t a, uint32_t b) {
    float s = __uint_as_float(a) + __uint_as_float(b);
    uint32_t o;
    asm("cvt.rna.tf32.f32 %0, %1;" : "=r"(o) : "f"(s));
    return o;
}
__device__ __forceinline__ void cp16(uint32_t dst, const void* src) {
    asm volatile("cp.async.cg.shared.global [%0], [%1], 16;" :: "r"(dst), "l"(src));
}
#define CP_COMMIT() asm volatile("cp.async.commit_group;" ::: "memory")
#define CP_WAIT1()  asm volatile("cp.async.wait_group 1;" ::: "memory")
#define CP_WAIT0()  asm volatile("cp.async.wait_group 0;" ::: "memory")

__device__ __forceinline__ void ldsm4(uint32_t r[4], uint32_t addr) {
    asm volatile("ldmatrix.sync.aligned.m8n8.x4.shared.b16 {%0,%1,%2,%3}, [%4];"
        : "=r"(r[0]), "=r"(r[1]), "=r"(r[2]), "=r"(r[3]) : "r"(addr));
}
__device__ __forceinline__ void ldsm2(uint32_t r[2], uint32_t addr) {
    asm volatile("ldmatrix.sync.aligned.m8n8.x2.shared.b16 {%0,%1}, [%2];"
        : "=r"(r[0]), "=r"(r[1]) : "r"(addr));
}
__device__ __forceinline__ void mma_tf32(float c[4], const uint32_t a[4], const uint32_t b[2]) {
    asm volatile("mma.sync.aligned.m16n8k8.row.col.f32.tf32.tf32.f32 "
        "{%0,%1,%2,%3},{%4,%5,%6,%7},{%8,%9},{%0,%1,%2,%3};"
        : "+f"(c[0]), "+f"(c[1]), "+f"(c[2]), "+f"(c[3])
        : "r"(a[0]), "r"(a[1]), "r"(a[2]), "r"(a[3]), "r"(b[0]), "r"(b[1]));
}

// 128x32 fp32 tile, 128B rows, XOR-swizzled 16B chunks. THREADS = block size.
template <int THREADS>
__device__ __forceinline__ void cpaf(const float* __restrict__ src,
                                     int row0, int k0, uint32_t smt, int tid) {
#pragma unroll
    for (int it = 0; it < 1024 / THREADS; ++it) {
        int c = tid + it * THREADS;
        int r = c >> 3, ch = c & 7;
        cp16(smt + r * 128 + ((ch ^ (r & 7)) << 4),
             src + (size_t)(row0 + r) * DIM + k0 + ch * 4);
    }
}

// ---------------- prep kernels ----------------
__global__ void perm_kernel() {
    int j = blockIdx.x * blockDim.x + threadIdx.x;
    if (j >= DIM) return;
    int idx = j;
#pragma unroll
    for (int i = NW - 1; i >= 0; --i) {
        int c = i, t = (i + 1) % NW;
        int cb = (idx >> (NW - 1 - c)) & 1;
        idx ^= cb << (NW - 1 - t);
    }
    g_invperm[idx] = j;    // idx = perm[j]  =>  invperm[perm[j]] = j
}

__global__ void norm_kernel(const float* __restrict__ x) {
    int b = blockIdx.x;
    const float4* xr = (const float4*)(x + (size_t)b * DIM);
    float s = 0.f;
    for (int i = threadIdx.x; i < DIM / 4; i += blockDim.x) {
        float4 v = xr[i];
        s += v.x * v.x + v.y * v.y + v.z * v.z + v.w * v.w;
    }
    __shared__ float red[4];
#pragma unroll
    for (int o = 16; o > 0; o >>= 1) s += __shfl_down_sync(0xffffffffu, s, o);
    if ((threadIdx.x & 31) == 0) red[threadIdx.x >> 5] = s;
    __syncthreads();
    if (threadIdx.x == 0) g_norm[b] = sqrtf(red[0] + red[1] + red[2] + red[3]);
}

// ---------------------------------------------------------------------------
// GEMM1 (tf32, raw inputs): s1 = U·x ; epilogue scatters to permuted rows.
// 256 threads, 8 warps, 64x32 warp tiles. smem: 0 Ur, 1 Ui, 2 X.
// ---------------------------------------------------------------------------
__global__ __launch_bounds__(256, 1)
void gemm1_kernel(const float* __restrict__ Ure,
                  const float* __restrict__ Uim,
                  const float* __restrict__ X) {
    extern __shared__ char smem[];
    uint32_t sbase = (uint32_t)__cvta_generic_to_shared(smem);
    const int tid = threadIdx.x, lane = tid & 31, wid = tid >> 5;
    const int g = lane >> 2, tg = lane & 3;
    const int wm0 = (wid >> 2) * 64, wn0 = (wid & 3) * 32;
    const int m0 = blockIdx.y * 128, n0 = blockIdx.x * 128;

    float cr[4][4][4], ci[4][4][4];
#pragma unroll
    for (int a = 0; a < 4; ++a)
#pragma unroll
        for (int b = 0; b < 4; ++b)
#pragma unroll
            for (int c = 0; c < 4; ++c) { cr[a][b][c] = 0.f; ci[a][b][c] = 0.f; }

    uint32_t apre[4], axor[4], bpre[4], bxor[4];
#pragma unroll
    for (int mt = 0; mt < 4; ++mt) {
        int r = wm0 + mt * 16 + (lane & 15);
        apre[mt] = r * 128;
        axor[mt] = (r & 7) << 4;
    }
#pragma unroll
    for (int nt = 0; nt < 4; ++nt) {
        int r = wn0 + nt * 8 + (lane & 7);
        bpre[nt] = r * 128;
        bxor[nt] = (r & 7) << 4;
    }
    const uint32_t ahalf = (lane >> 4) << 4;
    const uint32_t bhalf = ((lane >> 3) & 1) << 4;

#define G1_LOAD(st, t) do {                                \
    uint32_t _sb = sbase + (st) * G1S; int _k0 = (t) * BK;  \
    cpaf<256>(Ure, m0, _k0, _sb + 0 * TS, tid);             \
    cpaf<256>(Uim, m0, _k0, _sb + 1 * TS, tid);             \
    cpaf<256>(X,   n0, _k0, _sb + 2 * TS, tid);             \
} while (0)

    G1_LOAD(0, 0); CP_COMMIT();
    for (int t = 0; t < NS; ++t) {
        if (t + 1 < NS) { G1_LOAD((t + 1) & 1, t + 1); CP_COMMIT(); CP_WAIT1(); }
        else CP_WAIT0();
        __syncthreads();
        uint32_t sb = sbase + (t & 1) * G1S;
#pragma unroll
        for (int j = 0; j < 4; ++j) {
            const uint32_t ko = j * 32;
            uint32_t bv[4][2], av[4][4];
#pragma unroll
            for (int nt = 0; nt < 4; ++nt) {
                ldsm2(bv[nt], sb + 2 * TS + bpre[nt] + ((ko + bhalf) ^ bxor[nt]));
                cvtf(bv[nt][0]); cvtf(bv[nt][1]);
            }
#pragma unroll
            for (int mt = 0; mt < 4; ++mt) {
                ldsm4(av[mt], sb + 0 * TS + apre[mt] + ((ko + ahalf) ^ axor[mt]));
#pragma unroll
                for (int r = 0; r < 4; ++r) cvtf(av[mt][r]);
            }
#pragma unroll
            for (int mt = 0; mt < 4; ++mt)
#pragma unroll
                for (int nt = 0; nt < 4; ++nt) mma_tf32(cr[mt][nt], av[mt], bv[nt]);
#pragma unroll
            for (int mt = 0; mt < 4; ++mt) {
                ldsm4(av[mt], sb + 1 * TS + apre[mt] + ((ko + ahalf) ^ axor[mt]));
#pragma unroll
                for (int r = 0; r < 4; ++r) cvtf(av[mt][r]);
            }
#pragma unroll
            for (int mt = 0; mt < 4; ++mt)
#pragma unroll
                for (int nt = 0; nt < 4; ++nt) mma_tf32(ci[mt][nt], av[mt], bv[nt]);
        }
        __syncthreads();
    }
#undef G1_LOAD

    // epilogue: scatter to permuted row, raw fp32
#pragma unroll
    for (int mt = 0; mt < 4; ++mt)
#pragma unroll
        for (int nt = 0; nt < 4; ++nt)
#pragma unroll
            for (int c = 0; c < 4; ++c) {
                const int m = m0 + wm0 + mt * 16 + g + ((c >> 1) << 3);
                const int b = n0 + wn0 + nt * 8 + tg * 2 + (c & 1);
                const int row = g_invperm[m];
                const size_t o = (size_t)b * DIM + row;
                g_sr[o] = cr[mt][nt][c];
                g_si[o] = ci[mt][nt][c];
            }
}

// ---------------------------------------------------------------------------
// GEMM2 (tf32 Karatsuba, raw inputs, sums in registers):
// T1=Br·Sr, T2=Bi·Si, T3=rna(Br+Bi)·rna(Sr+Si); re=T1-T2, im=T3-T1-T2.
// 512 threads, 16 warps, 32x32 warp tiles. smem: 0 Br, 1 Bi, 2 Sr, 3 Si.
// ---------------------------------------------------------------------------
__global__ __launch_bounds__(512, 1)
void gemm2_kernel(const float* __restrict__ U1re,
                  const float* __restrict__ U1im,
                  float* __restrict__ out) {
    extern __shared__ char smem[];
    uint32_t sbase = (uint32_t)__cvta_generic_to_shared(smem);
    const int tid = threadIdx.x, lane = tid & 31, wid = tid >> 5;
    const int g = lane >> 2, tg = lane & 3;
    const int wm0 = (wid >> 2) * 32, wn0 = (wid & 3) * 32;
    const int m0 = blockIdx.y * 128, n0 = blockIdx.x * 128;

    float acc[3][2][4][4];
#pragma unroll
    for (int p = 0; p < 3; ++p)
#pragma unroll
        for (int a = 0; a < 2; ++a)
#pragma unroll
            for (int b = 0; b < 4; ++b)
#pragma unroll
                for (int c = 0; c < 4; ++c) acc[p][a][b][c] = 0.f;

    uint32_t apre[2], axor[2], bpre[4], bxor[4];
#pragma unroll
    for (int mt = 0; mt < 2; ++mt) {
        int r = wm0 + mt * 16 + (lane & 15);
        apre[mt] = r * 128;
        axor[mt] = (r & 7) << 4;
    }
#pragma unroll
    for (int nt = 0; nt < 4; ++nt) {
        int r = wn0 + nt * 8 + (lane & 7);
        bpre[nt] = r * 128;
        bxor[nt] = (r & 7) << 4;
    }
    const uint32_t ahalf = (lane >> 4) << 4;
    const uint32_t bhalf = ((lane >> 3) & 1) << 4;

#define G2_LOAD(st, t) do {                                \
    uint32_t _sb = sbase + (st) * G2S; int _k0 = (t) * BK;  \
    cpaf<512>(U1re, m0, _k0, _sb + 0 * TS, tid);            \
    cpaf<512>(U1im, m0, _k0, _sb + 1 * TS, tid);            \
    cpaf<512>(g_sr, n0, _k0, _sb + 2 * TS, tid);            \
    cpaf<512>(g_si, n0, _k0, _sb + 3 * TS, tid);            \
} while (0)

    G2_LOAD(0, 0); CP_COMMIT();
    for (int t = 0; t < NS; ++t) {
        if (t + 1 < NS) { G2_LOAD((t + 1) & 1, t + 1); CP_COMMIT(); CP_WAIT1(); }
        else CP_WAIT0();
        __syncthreads();
        uint32_t sb = sbase + (t & 1) * G2S;
#pragma unroll
        for (int j = 0; j < 4; ++j) {
            const uint32_t ko = j * 32;
            uint32_t br_[2][4], bi_[2][4], ap_[2][4];
#pragma unroll
            for (int mt = 0; mt < 2; ++mt) {
                ldsm4(br_[mt], sb + 0 * TS + apre[mt] + ((ko + ahalf) ^ axor[mt]));
                ldsm4(bi_[mt], sb + 1 * TS + apre[mt] + ((ko + ahalf) ^ axor[mt]));
#pragma unroll
                for (int r = 0; r < 4; ++r) {
                    ap_[mt][r] = addcvt(br_[mt][r], bi_[mt][r]);
                    cvtf(br_[mt][r]); cvtf(bi_[mt][r]);
                }
            }
            uint32_t sr_[4][2], si_[4][2], sp_[4][2];
#pragma unroll
            for (int nt = 0; nt < 4; ++nt) {
                ldsm2(sr_[nt], sb + 2 * TS + bpre[nt] + ((ko + bhalf) ^ bxor[nt]));
                ldsm2(si_[nt], sb + 3 * TS + bpre[nt] + ((ko + bhalf) ^ bxor[nt]));
#pragma unroll
                for (int r = 0; r < 2; ++r) {
                    sp_[nt][r] = addcvt(sr_[nt][r], si_[nt][r]);
                    cvtf(sr_[nt][r]); cvtf(si_[nt][r]);
                }
            }
#pragma unroll
            for (int mt = 0; mt < 2; ++mt)
#pragma unroll
                for (int nt = 0; nt < 4; ++nt) {
                    mma_tf32(acc[0][mt][nt], br_[mt], sr_[nt]);
                    mma_tf32(acc[1][mt][nt], bi_[mt], si_[nt]);
                    mma_tf32(acc[2][mt][nt], ap_[mt], sp_[nt]);
                }
        }
        __syncthreads();
    }
#undef G2_LOAD

#pragma unroll
    for (int mt = 0; mt < 2; ++mt)
#pragma unroll
        for (int nt = 0; nt < 4; ++nt)
#pragma unroll
            for (int c = 0; c < 4; ++c) {
                const int i = m0 + wm0 + mt * 16 + g + ((c >> 1) << 3);
                const int b = n0 + wn0 + nt * 8 + tg * 2 + (c & 1);
                const float t1 = acc[0][mt][nt][c];
                const float t2 = acc[1][mt][nt][c];
                const float t3 = acc[2][mt][nt][c];
                const float re = t1 - t2;
                const float im = t3 - t1 - t2;
                out[(size_t)b * DIM + i] = sqrtf(re * re + im * im) / g_norm[b];
            }
}

// ---------------------------------------------------------------------------
extern "C" void kernel_launch(void* const* d_in, const int* in_sizes, int n_in,
                              void* d_out, int out_size) {
    const float* x     = (const float*)d_in[0];
    const float* U_re  = (const float*)d_in[1];
    const float* U_im  = (const float*)d_in[2];
    const float* U1_re = (const float*)d_in[3];
    const float* U1_im = (const float*)d_in[4];
    float* out = (float*)d_out;

    cudaFuncSetAttribute(gemm1_kernel, cudaFuncAttributeMaxDynamicSharedMemorySize, 2 * G1S);
    cudaFuncSetAttribute(gemm2_kernel, cudaFuncAttributeMaxDynamicSharedMemorySize, 2 * G2S);

    perm_kernel<<<DIM / 256, 256>>>();
    norm_kernel<<<BSZ, 128>>>(x);

    dim3 grid(BSZ / 128, DIM / 128);   // (8, 32)
    gemm1_kernel<<<grid, 256, 2 * G1S>>>(U_re, U_im, x);
    gemm2_kernel<<<grid, 512, 2 * G2S>>>(U1_re, U1_im, out);
}

// round 10
// speedup vs baseline: 1.4485x; 1.4485x over previous
#include <cuda_runtime.h>
#include <math.h>
#include <stdint.h>

#define DIM 4096
#define BSZ 1024
#define NW  12
#define BK  32                 // fp32 elems per tile row = 128B
#define NS  (DIM / BK)
#define TS  (128 * 128)        // bytes per 128x32 fp32 tile
#define G1S (3 * TS)           // gemm1 stage: Ar, Ai, X
#define G2S (6 * TS)           // gemm2 stage: Br, Bi, Bp, Sr, Si, Sp

// ---------------- device-global scratch (tf32-rounded fp32) ----------------
__device__ __align__(16) float g_Ar[(size_t)DIM * DIM];   // permuted U_re
__device__ __align__(16) float g_Ai[(size_t)DIM * DIM];   // permuted U_im
__device__ __align__(16) float g_Br[(size_t)DIM * DIM];   // U1_re
__device__ __align__(16) float g_Bi[(size_t)DIM * DIM];   // U1_im
__device__ __align__(16) float g_Bp[(size_t)DIM * DIM];   // U1_re+U1_im
__device__ __align__(16) float g_x [(size_t)BSZ * DIM];
__device__ __align__(16) float g_sr[(size_t)BSZ * DIM];   // state re  [b][k]
__device__ __align__(16) float g_si[(size_t)BSZ * DIM];   // state im
__device__ __align__(16) float g_sp[(size_t)BSZ * DIM];   // re+im
__device__ int   g_perm[DIM];
__device__ float g_norm[BSZ];

// ---------------- helpers ----------------
__device__ __forceinline__ float tf32r(float v) {
    uint32_t u;
    asm("cvt.rna.tf32.f32 %0, %1;" : "=r"(u) : "f"(v));
    return __uint_as_float(u);
}
__device__ __forceinline__ float4 tf32r4(float4 v) {
    float4 o;
    o.x = tf32r(v.x); o.y = tf32r(v.y); o.z = tf32r(v.z); o.w = tf32r(v.w);
    return o;
}
__device__ __forceinline__ void cp16(uint32_t dst, const void* src) {
    asm volatile("cp.async.cg.shared.global [%0], [%1], 16;" :: "r"(dst), "l"(src));
}
#define CP_COMMIT() asm volatile("cp.async.commit_group;" ::: "memory")
#define CP_WAIT1()  asm volatile("cp.async.wait_group 1;" ::: "memory")
#define CP_WAIT0()  asm volatile("cp.async.wait_group 0;" ::: "memory")

__device__ __forceinline__ void ldsm4(uint32_t r[4], uint32_t addr) {
    asm volatile("ldmatrix.sync.aligned.m8n8.x4.shared.b16 {%0,%1,%2,%3}, [%4];"
        : "=r"(r[0]), "=r"(r[1]), "=r"(r[2]), "=r"(r[3]) : "r"(addr));
}
__device__ __forceinline__ void ldsm2(uint32_t r[2], uint32_t addr) {
    asm volatile("ldmatrix.sync.aligned.m8n8.x2.shared.b16 {%0,%1}, [%2];"
        : "=r"(r[0]), "=r"(r[1]) : "r"(addr));
}
__device__ __forceinline__ void mma_tf32(float c[4], const uint32_t a[4], const uint32_t b[2]) {
    asm volatile("mma.sync.aligned.m16n8k8.row.col.f32.tf32.tf32.f32 "
        "{%0,%1,%2,%3},{%4,%5,%6,%7},{%8,%9},{%0,%1,%2,%3};"
        : "+f"(c[0]), "+f"(c[1]), "+f"(c[2]), "+f"(c[3])
        : "r"(a[0]), "r"(a[1]), "r"(a[2]), "r"(a[3]), "r"(b[0]), "r"(b[1]));
}
#define MMA_BLK(C, A, B) do {                            \
    _Pragma("unroll") for (int _mt = 0; _mt < 4; ++_mt)   \
    _Pragma("unroll") for (int _nt = 0; _nt < 4; ++_nt)   \
        mma_tf32(C[_mt][_nt], A[_mt], B[_nt]);            \
} while (0)

// 128x32 fp32 tile, 128B rows, XOR-swizzled 16B chunks (ch ^= r&7)
__device__ __forceinline__ void cpaf(const float* __restrict__ src,
                                     int row0, int k0, uint32_t smt, int tid) {
#pragma unroll
    for (int it = 0; it < 4; ++it) {
        int c = tid + it * 256;
        int r = c >> 3, ch = c & 7;
        cp16(smt + r * 128 + ((ch ^ (r & 7)) << 4),
             src + (size_t)(row0 + r) * DIM + k0 + ch * 4);
    }
}

// ---------------- prep kernels ----------------
__global__ void perm_kernel() {
    int j = blockIdx.x * blockDim.x + threadIdx.x;
    if (j >= DIM) return;
    int idx = j;
#pragma unroll
    for (int i = NW - 1; i >= 0; --i) {
        int c = i, t = (i + 1) % NW;
        int cb = (idx >> (NW - 1 - c)) & 1;
        idx ^= cb << (NW - 1 - t);
    }
    g_perm[j] = idx;   // out_state[j] = in_state[perm[j]]
}

__global__ void norm_kernel(const float* __restrict__ x) {
    int b = blockIdx.x;
    const float4* xr = (const float4*)(x + (size_t)b * DIM);
    float s = 0.f;
    for (int i = threadIdx.x; i < DIM / 4; i += blockDim.x) {
        float4 v = xr[i];
        s += v.x * v.x + v.y * v.y + v.z * v.z + v.w * v.w;
    }
    __shared__ float red[4];
#pragma unroll
    for (int o = 16; o > 0; o >>= 1) s += __shfl_down_sync(0xffffffffu, s, o);
    if ((threadIdx.x & 31) == 0) red[threadIdx.x >> 5] = s;
    __syncthreads();
    if (threadIdx.x == 0) g_norm[b] = sqrtf(red[0] + red[1] + red[2] + red[3]);
}

// use_perm=1: permuted row-gather U -> Ar/Ai. use_perm=0: U1 -> Br/Bi/Bp.
// Fully unrolled, loads hoisted (MLP 8) to saturate HBM.
__global__ __launch_bounds__(256) void conv_u_kernel(
        const float* __restrict__ Ure, const float* __restrict__ Uim, int use_perm) {
    int j = blockIdx.x;
    int src = use_perm ? g_perm[j] : j;
    const float4* pr = (const float4*)(Ure + (size_t)src * DIM);
    const float4* pi = (const float4*)(Uim + (size_t)src * DIM);
    float4* dr = (float4*)((use_perm ? g_Ar : g_Br) + (size_t)j * DIM);
    float4* di = (float4*)((use_perm ? g_Ai : g_Bi) + (size_t)j * DIM);
    float4* dp = (float4*)(g_Bp + (size_t)j * DIM);

    float4 v[4], w[4];
    int c0 = threadIdx.x;
#pragma unroll
    for (int it = 0; it < 4; ++it) v[it] = __ldg(&pr[c0 + it * 256]);
#pragma unroll
    for (int it = 0; it < 4; ++it) w[it] = __ldg(&pi[c0 + it * 256]);
#pragma unroll
    for (int it = 0; it < 4; ++it) {
        int c = c0 + it * 256;
        dr[c] = tf32r4(v[it]);
        di[c] = tf32r4(w[it]);
        if (!use_perm) {
            float4 p;
            p.x = tf32r(v[it].x + w[it].x); p.y = tf32r(v[it].y + w[it].y);
            p.z = tf32r(v[it].z + w[it].z); p.w = tf32r(v[it].w + w[it].w);
            dp[c] = p;
        }
    }
}

__global__ __launch_bounds__(256) void conv_x_kernel(const float* __restrict__ x) {
    int b = blockIdx.x;
    const float4* px = (const float4*)(x + (size_t)b * DIM);
    float4* dh = (float4*)(g_x + (size_t)b * DIM);
    float4 v[4];
    int c0 = threadIdx.x;
#pragma unroll
    for (int it = 0; it < 4; ++it) v[it] = __ldg(&px[c0 + it * 256]);
#pragma unroll
    for (int it = 0; it < 4; ++it) dh[c0 + it * 256] = tf32r4(v[it]);
}

// ---------------------------------------------------------------------------
// GEMM1 (tf32): s[j,b] = Uperm_re[j,:]·x[b,:] (+ i Uperm_im·x).
// Epilogue: tf32-rounded sr, si, sp=re+im stored [b][k].
// smem arrays: 0 Ar, 1 Ai, 2 X.
// ---------------------------------------------------------------------------
__global__ __launch_bounds__(256, 1) void gemm1_kernel() {
    extern __shared__ char smem[];
    uint32_t sbase = (uint32_t)__cvta_generic_to_shared(smem);
    const int tid = threadIdx.x, lane = tid & 31, wid = tid >> 5;
    const int g = lane >> 2, tg = lane & 3;
    const int wm0 = (wid >> 2) * 64, wn0 = (wid & 3) * 32;
    const int m0 = blockIdx.y * 128, n0 = blockIdx.x * 128;

    float cr[4][4][4], ci[4][4][4];
#pragma unroll
    for (int a = 0; a < 4; ++a)
#pragma unroll
        for (int b = 0; b < 4; ++b)
#pragma unroll
            for (int c = 0; c < 4; ++c) { cr[a][b][c] = 0.f; ci[a][b][c] = 0.f; }

    uint32_t apre[4], axor[4], bpre[4], bxor[4];
#pragma unroll
    for (int mt = 0; mt < 4; ++mt) {
        int r = wm0 + mt * 16 + (lane & 15);
        apre[mt] = r * 128;
        axor[mt] = (r & 7) << 4;
    }
#pragma unroll
    for (int nt = 0; nt < 4; ++nt) {
        int r = wn0 + nt * 8 + (lane & 7);
        bpre[nt] = r * 128;
        bxor[nt] = (r & 7) << 4;
    }
    const uint32_t ahalf = (lane >> 4) << 4;
    const uint32_t bhalf = ((lane >> 3) & 1) << 4;

#define G1_LOAD(st, t) do {                                \
    uint32_t _sb = sbase + (st) * G1S; int _k0 = (t) * BK;  \
    cpaf(g_Ar, m0, _k0, _sb + 0 * TS, tid);                 \
    cpaf(g_Ai, m0, _k0, _sb + 1 * TS, tid);                 \
    cpaf(g_x,  n0, _k0, _sb + 2 * TS, tid);                 \
} while (0)

    G1_LOAD(0, 0); CP_COMMIT();
    for (int t = 0; t < NS; ++t) {
        if (t + 1 < NS) { G1_LOAD((t + 1) & 1, t + 1); CP_COMMIT(); CP_WAIT1(); }
        else CP_WAIT0();
        __syncthreads();
        uint32_t sb = sbase + (t & 1) * G1S;
#pragma unroll
        for (int j = 0; j < 4; ++j) {                 // 4 k8 steps per k32
            const uint32_t ko = j * 32;
            uint32_t bv[4][2], av[4][4];
#pragma unroll
            for (int nt = 0; nt < 4; ++nt)
                ldsm2(bv[nt], sb + 2 * TS + bpre[nt] + ((ko + bhalf) ^ bxor[nt]));
#pragma unroll
            for (int mt = 0; mt < 4; ++mt)
                ldsm4(av[mt], sb + 0 * TS + apre[mt] + ((ko + ahalf) ^ axor[mt]));
            MMA_BLK(cr, av, bv);
#pragma unroll
            for (int mt = 0; mt < 4; ++mt)
                ldsm4(av[mt], sb + 1 * TS + apre[mt] + ((ko + ahalf) ^ axor[mt]));
            MMA_BLK(ci, av, bv);
        }
        __syncthreads();
    }
#undef G1_LOAD

#pragma unroll
    for (int mt = 0; mt < 4; ++mt)
#pragma unroll
        for (int nt = 0; nt < 4; ++nt)
#pragma unroll
            for (int c = 0; c < 4; ++c) {
                const int m = m0 + wm0 + mt * 16 + g + ((c >> 1) << 3);
                const int b = n0 + wn0 + nt * 8 + tg * 2 + (c & 1);
                const size_t o = (size_t)b * DIM + m;
                const float re = cr[mt][nt][c], im = ci[mt][nt][c];
                g_sr[o] = tf32r(re);
                g_si[o] = tf32r(im);
                g_sp[o] = tf32r(re + im);
            }
}

// ---------------------------------------------------------------------------
// GEMM2 (tf32, Karatsuba 3M): T1=Br·Sr, T2=Bi·Si, T3=Bp·Sp
// re = T1-T2, im = T3-T1-T2 ; out = |.|/norm.
// smem arrays: 0 Br, 1 Bi, 2 Bp, 3 Sr, 4 Si, 5 Sp.
// ---------------------------------------------------------------------------
__global__ __launch_bounds__(256, 1) void gemm2_kernel(float* __restrict__ out) {
    extern __shared__ char smem[];
    uint32_t sbase = (uint32_t)__cvta_generic_to_shared(smem);
    const int tid = threadIdx.x, lane = tid & 31, wid = tid >> 5;
    const int g = lane >> 2, tg = lane & 3;
    const int wm0 = (wid >> 2) * 64, wn0 = (wid & 3) * 32;
    const int m0 = blockIdx.y * 128, n0 = blockIdx.x * 128;

    float acc[3][4][4][4];
#pragma unroll
    for (int p = 0; p < 3; ++p)
#pragma unroll
        for (int a = 0; a < 4; ++a)
#pragma unroll
            for (int b = 0; b < 4; ++b)
#pragma unroll
                for (int c = 0; c < 4; ++c) acc[p][a][b][c] = 0.f;

    uint32_t apre[4], axor[4], bpre[4], bxor[4];
#pragma unroll
    for (int mt = 0; mt < 4; ++mt) {
        int r = wm0 + mt * 16 + (lane & 15);
        apre[mt] = r * 128;
        axor[mt] = (r & 7) << 4;
    }
#pragma unroll
    for (int nt = 0; nt < 4; ++nt) {
        int r = wn0 + nt * 8 + (lane & 7);
        bpre[nt] = r * 128;
        bxor[nt] = (r & 7) << 4;
    }
    const uint32_t ahalf = (lane >> 4) << 4;
    const uint32_t bhalf = ((lane >> 3) & 1) << 4;

#define G2_LOAD(st, t) do {                                \
    uint32_t _sb = sbase + (st) * G2S; int _k0 = (t) * BK;  \
    cpaf(g_Br, m0, _k0, _sb + 0 * TS, tid);                 \
    cpaf(g_Bi, m0, _k0, _sb + 1 * TS, tid);                 \
    cpaf(g_Bp, m0, _k0, _sb + 2 * TS, tid);                 \
    cpaf(g_sr, n0, _k0, _sb + 3 * TS, tid);                 \
    cpaf(g_si, n0, _k0, _sb + 4 * TS, tid);                 \
    cpaf(g_sp, n0, _k0, _sb + 5 * TS, tid);                 \
} while (0)

    G2_LOAD(0, 0); CP_COMMIT();
    for (int t = 0; t < NS; ++t) {
        if (t + 1 < NS) { G2_LOAD((t + 1) & 1, t + 1); CP_COMMIT(); CP_WAIT1(); }
        else CP_WAIT0();
        __syncthreads();
        uint32_t sb = sbase + (t & 1) * G2S;
#pragma unroll
        for (int j = 0; j < 4; ++j) {
            const uint32_t ko = j * 32;
#pragma unroll
            for (int p = 0; p < 3; ++p) {
                uint32_t av[4][4], bv[4][2];
#pragma unroll
                for (int mt = 0; mt < 4; ++mt)
                    ldsm4(av[mt], sb + p * TS + apre[mt] + ((ko + ahalf) ^ axor[mt]));
#pragma unroll
                for (int nt = 0; nt < 4; ++nt)
                    ldsm2(bv[nt], sb + (3 + p) * TS + bpre[nt] + ((ko + bhalf) ^ bxor[nt]));
                MMA_BLK(acc[p], av, bv);
            }
        }
        __syncthreads();
    }
#undef G2_LOAD

#pragma unroll
    for (int mt = 0; mt < 4; ++mt)
#pragma unroll
        for (int nt = 0; nt < 4; ++nt)
#pragma unroll
            for (int c = 0; c < 4; ++c) {
                const int i = m0 + wm0 + mt * 16 + g + ((c >> 1) << 3);
                const int b = n0 + wn0 + nt * 8 + tg * 2 + (c & 1);
                const float t1 = acc[0][mt][nt][c];
                const float t2 = acc[1][mt][nt][c];
                const float t3 = acc[2][mt][nt][c];
                const float re = t1 - t2;
                const float im = t3 - t1 - t2;
                out[(size_t)b * DIM + i] = sqrtf(re * re + im * im) / g_norm[b];
            }
}

// ---------------------------------------------------------------------------
extern "C" void kernel_launch(void* const* d_in, const int* in_sizes, int n_in,
                              void* d_out, int out_size) {
    const float* x     = (const float*)d_in[0];
    const float* U_re  = (const float*)d_in[1];
    const float* U_im  = (const float*)d_in[2];
    const float* U1_re = (const float*)d_in[3];
    const float* U1_im = (const float*)d_in[4];
    float* out = (float*)d_out;

    cudaFuncSetAttribute(gemm1_kernel, cudaFuncAttributeMaxDynamicSharedMemorySize, 2 * G1S);
    cudaFuncSetAttribute(gemm2_kernel, cudaFuncAttributeMaxDynamicSharedMemorySize, 2 * G2S);

    perm_kernel<<<DIM / 256, 256>>>();
    norm_kernel<<<BSZ, 128>>>(x);
    conv_u_kernel<<<DIM, 256>>>(U_re, U_im, 1);
    conv_u_kernel<<<DIM, 256>>>(U1_re, U1_im, 0);
    conv_x_kernel<<<BSZ, 256>>>(x);

    dim3 grid(BSZ / 128, DIM / 128);   // (8, 32)
    gemm1_kernel<<<grid, 256, 2 * G1S>>>();
    gemm2_kernel<<<grid, 256, 2 * G2S>>>(out);
}

// round 11
// speedup vs baseline: 2.6834x; 1.8526x over previous
#include <cuda_runtime.h>
#include <cuda_fp16.h>
#include <math.h>
#include <stdint.h>

#define DIM 4096
#define BSZ 1024
#define NW  12
#define BK  64                 // halves per tile row = 128B
#define NS  (DIM / BK)         // 64
#define TS  (128 * 128)        // bytes per 128x64 half tile
#define G1S (3 * TS)           // gemm1 stage: Ar, Ai, X
#define G2S (6 * TS)           // gemm2 stage: Br, Bi, Bp, Sr, Si, Sp

// ---------------- device-global scratch (fp16) ----------------
__device__ __align__(16) __half g_Ar[(size_t)DIM * DIM];   // permuted U_re
__device__ __align__(16) __half g_Ai[(size_t)DIM * DIM];   // permuted U_im
__device__ __align__(16) __half g_Br[(size_t)DIM * DIM];   // U1_re
__device__ __align__(16) __half g_Bi[(size_t)DIM * DIM];   // U1_im
__device__ __align__(16) __half g_Bp[(size_t)DIM * DIM];   // U1_re+U1_im
__device__ __align__(16) __half g_x [(size_t)BSZ * DIM];
__device__ __align__(16) __half g_sr[(size_t)BSZ * DIM];   // state re  [b][k]
__device__ __align__(16) __half g_si[(size_t)BSZ * DIM];   // state im
__device__ __align__(16) __half g_sp[(size_t)BSZ * DIM];   // re+im
__device__ int   g_perm[DIM];
__device__ float g_norm[BSZ];

// ---------------- helpers ----------------
__device__ __forceinline__ uint32_t pkh(float a, float b) {
    __half2 h = __floats2half2_rn(a, b);
    return *(uint32_t*)&h;
}
__device__ __forceinline__ uint2 pk4(float4 v) {
    return make_uint2(pkh(v.x, v.y), pkh(v.z, v.w));
}
__device__ __forceinline__ void cp16(uint32_t dst, const void* src) {
    asm volatile("cp.async.cg.shared.global [%0], [%1], 16;" :: "r"(dst), "l"(src));
}
#define CP_COMMIT() asm volatile("cp.async.commit_group;" ::: "memory")
#define CP_WAIT1()  asm volatile("cp.async.wait_group 1;" ::: "memory")
#define CP_WAIT0()  asm volatile("cp.async.wait_group 0;" ::: "memory")

__device__ __forceinline__ void ldsm4(uint32_t r[4], uint32_t addr) {
    asm volatile("ldmatrix.sync.aligned.m8n8.x4.shared.b16 {%0,%1,%2,%3}, [%4];"
        : "=r"(r[0]), "=r"(r[1]), "=r"(r[2]), "=r"(r[3]) : "r"(addr));
}
__device__ __forceinline__ void ldsm2(uint32_t r[2], uint32_t addr) {
    asm volatile("ldmatrix.sync.aligned.m8n8.x2.shared.b16 {%0,%1}, [%2];"
        : "=r"(r[0]), "=r"(r[1]) : "r"(addr));
}
__device__ __forceinline__ void mma_f16(float c[4], const uint32_t a[4], const uint32_t b[2]) {
    asm volatile("mma.sync.aligned.m16n8k16.row.col.f32.f16.f16.f32 "
        "{%0,%1,%2,%3},{%4,%5,%6,%7},{%8,%9},{%0,%1,%2,%3};"
        : "+f"(c[0]), "+f"(c[1]), "+f"(c[2]), "+f"(c[3])
        : "r"(a[0]), "r"(a[1]), "r"(a[2]), "r"(a[3]), "r"(b[0]), "r"(b[1]));
}
#define MMA_BLK(C, A, B) do {                            \
    _Pragma("unroll") for (int _mt = 0; _mt < 4; ++_mt)   \
    _Pragma("unroll") for (int _nt = 0; _nt < 4; ++_nt)   \
        mma_f16(C[_mt][_nt], A[_mt], B[_nt]);             \
} while (0)

// 128x64 half tile, 128B rows, XOR-swizzled 16B chunks (ch ^= r&7)
__device__ __forceinline__ void cpah(const __half* __restrict__ src,
                                     int row0, int k0, uint32_t smt, int tid) {
#pragma unroll
    for (int it = 0; it < 4; ++it) {
        int c = tid + it * 256;
        int r = c >> 3, ch = c & 7;
        cp16(smt + r * 128 + ((ch ^ (r & 7)) << 4),
             src + (size_t)(row0 + r) * DIM + k0 + ch * 8);
    }
}

// ---------------- prep kernels ----------------
__global__ void perm_kernel() {
    int j = blockIdx.x * blockDim.x + threadIdx.x;
    if (j >= DIM) return;
    int idx = j;
#pragma unroll
    for (int i = NW - 1; i >= 0; --i) {
        int c = i, t = (i + 1) % NW;
        int cb = (idx >> (NW - 1 - c)) & 1;
        idx ^= cb << (NW - 1 - t);
    }
    g_perm[j] = idx;   // out_state[j] = in_state[perm[j]]
}

__global__ void norm_kernel(const float* __restrict__ x) {
    int b = blockIdx.x;
    const float4* xr = (const float4*)(x + (size_t)b * DIM);
    float s = 0.f;
    for (int i = threadIdx.x; i < DIM / 4; i += blockDim.x) {
        float4 v = xr[i];
        s += v.x * v.x + v.y * v.y + v.z * v.z + v.w * v.w;
    }
    __shared__ float red[4];
#pragma unroll
    for (int o = 16; o > 0; o >>= 1) s += __shfl_down_sync(0xffffffffu, s, o);
    if ((threadIdx.x & 31) == 0) red[threadIdx.x >> 5] = s;
    __syncthreads();
    if (threadIdx.x == 0) g_norm[b] = sqrtf(red[0] + red[1] + red[2] + red[3]);
}

// use_perm=1: permuted row-gather U -> Ar/Ai. use_perm=0: U1 -> Br/Bi/Bp.
__global__ __launch_bounds__(256) void conv_u_kernel(
        const float* __restrict__ Ure, const float* __restrict__ Uim, int use_perm) {
    int j = blockIdx.x;
    int src = use_perm ? g_perm[j] : j;
    const float4* pr = (const float4*)(Ure + (size_t)src * DIM);
    const float4* pi = (const float4*)(Uim + (size_t)src * DIM);
    uint2* dr = (uint2*)((use_perm ? g_Ar : g_Br) + (size_t)j * DIM);
    uint2* di = (uint2*)((use_perm ? g_Ai : g_Bi) + (size_t)j * DIM);
    uint2* dp = (uint2*)(g_Bp + (size_t)j * DIM);

    float4 v[4], w[4];
    int c0 = threadIdx.x;
#pragma unroll
    for (int it = 0; it < 4; ++it) v[it] = __ldg(&pr[c0 + it * 256]);
#pragma unroll
    for (int it = 0; it < 4; ++it) w[it] = __ldg(&pi[c0 + it * 256]);
#pragma unroll
    for (int it = 0; it < 4; ++it) {
        int c = c0 + it * 256;
        dr[c] = pk4(v[it]);
        di[c] = pk4(w[it]);
        if (!use_perm) {
            float4 p;
            p.x = v[it].x + w[it].x; p.y = v[it].y + w[it].y;
            p.z = v[it].z + w[it].z; p.w = v[it].w + w[it].w;
            dp[c] = pk4(p);
        }
    }
}

__global__ __launch_bounds__(256) void conv_x_kernel(const float* __restrict__ x) {
    int b = blockIdx.x;
    const float4* px = (const float4*)(x + (size_t)b * DIM);
    uint2* dh = (uint2*)(g_x + (size_t)b * DIM);
    float4 v[4];
    int c0 = threadIdx.x;
#pragma unroll
    for (int it = 0; it < 4; ++it) v[it] = __ldg(&px[c0 + it * 256]);
#pragma unroll
    for (int it = 0; it < 4; ++it) dh[c0 + it * 256] = pk4(v[it]);
}

// ---------------------------------------------------------------------------
// GEMM1 (fp16 single-pass): s[j,b] = Uperm_re[j,:]·x[b,:] (+ i Uperm_im·x).
// Epilogue: fp16 sr, si, sp=re+im stored [b][k].  smem: 0 Ar, 1 Ai, 2 X.
// ---------------------------------------------------------------------------
__global__ __launch_bounds__(256, 1) void gemm1_kernel() {
    extern __shared__ char smem[];
    uint32_t sbase = (uint32_t)__cvta_generic_to_shared(smem);
    const int tid = threadIdx.x, lane = tid & 31, wid = tid >> 5;
    const int g = lane >> 2, tg = lane & 3;
    const int wm0 = (wid >> 2) * 64, wn0 = (wid & 3) * 32;
    const int m0 = blockIdx.y * 128, n0 = blockIdx.x * 128;

    float cr[4][4][4], ci[4][4][4];
#pragma unroll
    for (int a = 0; a < 4; ++a)
#pragma unroll
        for (int b = 0; b < 4; ++b)
#pragma unroll
            for (int c = 0; c < 4; ++c) { cr[a][b][c] = 0.f; ci[a][b][c] = 0.f; }

    uint32_t apre[4], axor[4], bpre[4], bxor[4];
#pragma unroll
    for (int mt = 0; mt < 4; ++mt) {
        int r = wm0 + mt * 16 + (lane & 15);
        apre[mt] = r * 128;
        axor[mt] = (r & 7) << 4;
    }
#pragma unroll
    for (int nt = 0; nt < 4; ++nt) {
        int r = wn0 + nt * 8 + (lane & 7);
        bpre[nt] = r * 128;
        bxor[nt] = (r & 7) << 4;
    }
    const uint32_t ahalf = (lane >> 4) << 4;        // k8 half select (16B)
    const uint32_t bhalf = ((lane >> 3) & 1) << 4;

#define G1_LOAD(st, t) do {                                \
    uint32_t _sb = sbase + (st) * G1S; int _k0 = (t) * BK;  \
    cpah(g_Ar, m0, _k0, _sb + 0 * TS, tid);                 \
    cpah(g_Ai, m0, _k0, _sb + 1 * TS, tid);                 \
    cpah(g_x,  n0, _k0, _sb + 2 * TS, tid);                 \
} while (0)

    G1_LOAD(0, 0); CP_COMMIT();
    for (int t = 0; t < NS; ++t) {
        if (t + 1 < NS) { G1_LOAD((t + 1) & 1, t + 1); CP_COMMIT(); CP_WAIT1(); }
        else CP_WAIT0();
        __syncthreads();
        uint32_t sb = sbase + (t & 1) * G1S;
#pragma unroll
        for (int j = 0; j < 4; ++j) {                 // 4 k16 steps per k64 tile
            const uint32_t ko = j * 32;               // 16 halves = 32B
            uint32_t bv[4][2], av[4][4];
#pragma unroll
            for (int nt = 0; nt < 4; ++nt)
                ldsm2(bv[nt], sb + 2 * TS + bpre[nt] + ((ko + bhalf) ^ bxor[nt]));
#pragma unroll
            for (int mt = 0; mt < 4; ++mt)
                ldsm4(av[mt], sb + 0 * TS + apre[mt] + ((ko + ahalf) ^ axor[mt]));
            MMA_BLK(cr, av, bv);
#pragma unroll
            for (int mt = 0; mt < 4; ++mt)
                ldsm4(av[mt], sb + 1 * TS + apre[mt] + ((ko + ahalf) ^ axor[mt]));
            MMA_BLK(ci, av, bv);
        }
        __syncthreads();
    }
#undef G1_LOAD

#pragma unroll
    for (int mt = 0; mt < 4; ++mt)
#pragma unroll
        for (int nt = 0; nt < 4; ++nt)
#pragma unroll
            for (int c = 0; c < 4; ++c) {
                const int m = m0 + wm0 + mt * 16 + g + ((c >> 1) << 3);
                const int b = n0 + wn0 + nt * 8 + tg * 2 + (c & 1);
                const size_t o = (size_t)b * DIM + m;
                const float re = cr[mt][nt][c], im = ci[mt][nt][c];
                g_sr[o] = __float2half_rn(re);
                g_si[o] = __float2half_rn(im);
                g_sp[o] = __float2half_rn(re + im);
            }
}

// ---------------------------------------------------------------------------
// GEMM2 (fp16, Karatsuba 3M): T1=Br·Sr, T2=Bi·Si, T3=Bp·Sp
// re = T1-T2, im = T3-T1-T2 ; out = |.|/norm.
// smem arrays: 0 Br, 1 Bi, 2 Bp, 3 Sr, 4 Si, 5 Sp.
// ---------------------------------------------------------------------------
__global__ __launch_bounds__(256, 1) void gemm2_kernel(float* __restrict__ out) {
    extern __shared__ char smem[];
    uint32_t sbase = (uint32_t)__cvta_generic_to_shared(smem);
    const int tid = threadIdx.x, lane = tid & 31, wid = tid >> 5;
    const int g = lane >> 2, tg = lane & 3;
    const int wm0 = (wid >> 2) * 64, wn0 = (wid & 3) * 32;
    const int m0 = blockIdx.y * 128, n0 = blockIdx.x * 128;

    float acc[3][4][4][4];
#pragma unroll
    for (int p = 0; p < 3; ++p)
#pragma unroll
        for (int a = 0; a < 4; ++a)
#pragma unroll
            for (int b = 0; b < 4; ++b)
#pragma unroll
                for (int c = 0; c < 4; ++c) acc[p][a][b][c] = 0.f;

    uint32_t apre[4], axor[4], bpre[4], bxor[4];
#pragma unroll
    for (int mt = 0; mt < 4; ++mt) {
        int r = wm0 + mt * 16 + (lane & 15);
        apre[mt] = r * 128;
        axor[mt] = (r & 7) << 4;
    }
#pragma unroll
    for (int nt = 0; nt < 4; ++nt) {
        int r = wn0 + nt * 8 + (lane & 7);
        bpre[nt] = r * 128;
        bxor[nt] = (r & 7) << 4;
    }
    const uint32_t ahalf = (lane >> 4) << 4;
    const uint32_t bhalf = ((lane >> 3) & 1) << 4;

#define G2_LOAD(st, t) do {                                \
    uint32_t _sb = sbase + (st) * G2S; int _k0 = (t) * BK;  \
    cpah(g_Br, m0, _k0, _sb + 0 * TS, tid);                 \
    cpah(g_Bi, m0, _k0, _sb + 1 * TS, tid);                 \
    cpah(g_Bp, m0, _k0, _sb + 2 * TS, tid);                 \
    cpah(g_sr, n0, _k0, _sb + 3 * TS, tid);                 \
    cpah(g_si, n0, _k0, _sb + 4 * TS, tid);                 \
    cpah(g_sp, n0, _k0, _sb + 5 * TS, tid);                 \
} while (0)

    G2_LOAD(0, 0); CP_COMMIT();
    for (int t = 0; t < NS; ++t) {
        if (t + 1 < NS) { G2_LOAD((t + 1) & 1, t + 1); CP_COMMIT(); CP_WAIT1(); }
        else CP_WAIT0();
        __syncthreads();
        uint32_t sb = sbase + (t & 1) * G2S;
#pragma unroll
        for (int j = 0; j < 4; ++j) {
            const uint32_t ko = j * 32;
#pragma unroll
            for (int p = 0; p < 3; ++p) {
                uint32_t av[4][4], bv[4][2];
#pragma unroll
                for (int mt = 0; mt < 4; ++mt)
                    ldsm4(av[mt], sb + p * TS + apre[mt] + ((ko + ahalf) ^ axor[mt]));
#pragma unroll
                for (int nt = 0; nt < 4; ++nt)
                    ldsm2(bv[nt], sb + (3 + p) * TS + bpre[nt] + ((ko + bhalf) ^ bxor[nt]));
                MMA_BLK(acc[p], av, bv);
            }
        }
        __syncthreads();
    }
#undef G2_LOAD

#pragma unroll
    for (int mt = 0; mt < 4; ++mt)
#pragma unroll
        for (int nt = 0; nt < 4; ++nt)
#pragma unroll
            for (int c = 0; c < 4; ++c) {
                const int i = m0 + wm0 + mt * 16 + g + ((c >> 1) << 3);
                const int b = n0 + wn0 + nt * 8 + tg * 2 + (c & 1);
                const float t1 = acc[0][mt][nt][c];
                const float t2 = acc[1][mt][nt][c];
                const float t3 = acc[2][mt][nt][c];
                const float re = t1 - t2;
                const float im = t3 - t1 - t2;
                out[(size_t)b * DIM + i] = sqrtf(re * re + im * im) / g_norm[b];
            }
}

// ---------------------------------------------------------------------------
extern "C" void kernel_launch(void* const* d_in, const int* in_sizes, int n_in,
                              void* d_out, int out_size) {
    const float* x     = (const float*)d_in[0];
    const float* U_re  = (const float*)d_in[1];
    const float* U_im  = (const float*)d_in[2];
    const float* U1_re = (const float*)d_in[3];
    const float* U1_im = (const float*)d_in[4];
    float* out = (float*)d_out;

    cudaFuncSetAttribute(gemm1_kernel, cudaFuncAttributeMaxDynamicSharedMemorySize, 2 * G1S);
    cudaFuncSetAttribute(gemm2_kernel, cudaFuncAttributeMaxDynamicSharedMemorySize, 2 * G2S);

    perm_kernel<<<DIM / 256, 256>>>();
    norm_kernel<<<BSZ, 128>>>(x);
    conv_u_kernel<<<DIM, 256>>>(U_re, U_im, 1);
    conv_u_kernel<<<DIM, 256>>>(U1_re, U1_im, 0);
    conv_x_kernel<<<BSZ, 256>>>(x);

    dim3 grid(BSZ / 128, DIM / 128);   // (8, 32)
    gemm1_kernel<<<grid, 256, 2 * G1S>>>();
    gemm2_kernel<<<grid, 256, 2 * G2S>>>(out);
}

// round 12
// speedup vs baseline: 2.8343x; 1.0562x over previous
#include <cuda_runtime.h>
#include <cuda_fp16.h>
#include <math.h>
#include <stdint.h>

#define DIM 4096
#define BSZ 1024
#define NW  12
#define BK  64                 // halves per tile row = 128B
#define NS  (DIM / BK)         // 64
#define TS  (128 * 128)        // bytes per 128x64 half tile
#define G1S (3 * TS)           // gemm1 stage: Ar, Ai, X
#define G2S (6 * TS)           // gemm2 stage: Br, Bi, Bp, Sr, Si, Sp
#define G1_TILES 256           // gemm1 compute blocks (8 n x 32 m)

// ---------------- device-global scratch (fp16) ----------------
__device__ __align__(16) __half g_Ar[(size_t)DIM * DIM];   // permuted U_re
__device__ __align__(16) __half g_Ai[(size_t)DIM * DIM];   // permuted U_im
__device__ __align__(16) __half g_Br[(size_t)DIM * DIM];   // U1_re
__device__ __align__(16) __half g_Bi[(size_t)DIM * DIM];   // U1_im
__device__ __align__(16) __half g_Bp[(size_t)DIM * DIM];   // U1_re+U1_im
__device__ __align__(16) __half g_x [(size_t)BSZ * DIM];
__device__ __align__(16) __half g_sr[(size_t)BSZ * DIM];   // state re  [b][k]
__device__ __align__(16) __half g_si[(size_t)BSZ * DIM];   // state im
__device__ __align__(16) __half g_sp[(size_t)BSZ * DIM];   // re+im
__device__ int   g_perm[DIM];
__device__ float g_norm[BSZ];

// ---------------- helpers ----------------
__device__ __forceinline__ uint32_t pkh(float a, float b) {
    __half2 h = __floats2half2_rn(a, b);
    return *(uint32_t*)&h;
}
__device__ __forceinline__ uint2 pk4(float4 v) {
    return make_uint2(pkh(v.x, v.y), pkh(v.z, v.w));
}
__device__ __forceinline__ void cp16(uint32_t dst, const void* src) {
    asm volatile("cp.async.cg.shared.global [%0], [%1], 16;" :: "r"(dst), "l"(src));
}
#define CP_COMMIT() asm volatile("cp.async.commit_group;" ::: "memory")
#define CP_WAIT1()  asm volatile("cp.async.wait_group 1;" ::: "memory")
#define CP_WAIT0()  asm volatile("cp.async.wait_group 0;" ::: "memory")

__device__ __forceinline__ void ldsm4(uint32_t r[4], uint32_t addr) {
    asm volatile("ldmatrix.sync.aligned.m8n8.x4.shared.b16 {%0,%1,%2,%3}, [%4];"
        : "=r"(r[0]), "=r"(r[1]), "=r"(r[2]), "=r"(r[3]) : "r"(addr));
}
__device__ __forceinline__ void ldsm2(uint32_t r[2], uint32_t addr) {
    asm volatile("ldmatrix.sync.aligned.m8n8.x2.shared.b16 {%0,%1}, [%2];"
        : "=r"(r[0]), "=r"(r[1]) : "r"(addr));
}
__device__ __forceinline__ void mma_f16(float c[4], const uint32_t a[4], const uint32_t b[2]) {
    asm volatile("mma.sync.aligned.m16n8k16.row.col.f32.f16.f16.f32 "
        "{%0,%1,%2,%3},{%4,%5,%6,%7},{%8,%9},{%0,%1,%2,%3};"
        : "+f"(c[0]), "+f"(c[1]), "+f"(c[2]), "+f"(c[3])
        : "r"(a[0]), "r"(a[1]), "r"(a[2]), "r"(a[3]), "r"(b[0]), "r"(b[1]));
}
#define MMA_BLK(C, A, B) do {                            \
    _Pragma("unroll") for (int _mt = 0; _mt < 4; ++_mt)   \
    _Pragma("unroll") for (int _nt = 0; _nt < 4; ++_nt)   \
        mma_f16(C[_mt][_nt], A[_mt], B[_nt]);             \
} while (0)

// 128x64 half tile, 128B rows, XOR-swizzled 16B chunks (ch ^= r&7)
__device__ __forceinline__ void cpah(const __half* __restrict__ src,
                                     int row0, int k0, uint32_t smt, int tid) {
#pragma unroll
    for (int it = 0; it < 4; ++it) {
        int c = tid + it * 256;
        int r = c >> 3, ch = c & 7;
        cp16(smt + r * 128 + ((ch ^ (r & 7)) << 4),
             src + (size_t)(row0 + r) * DIM + k0 + ch * 8);
    }
}

// ---------------- prep kernels ----------------
__global__ void perm_kernel() {
    int j = blockIdx.x * blockDim.x + threadIdx.x;
    if (j >= DIM) return;
    int idx = j;
#pragma unroll
    for (int i = NW - 1; i >= 0; --i) {
        int c = i, t = (i + 1) % NW;
        int cb = (idx >> (NW - 1 - c)) & 1;
        idx ^= cb << (NW - 1 - t);
    }
    g_perm[j] = idx;   // out_state[j] = in_state[perm[j]]
}

// norm + fp16 conversion of x in one pass
__global__ __launch_bounds__(256) void normx_kernel(const float* __restrict__ x) {
    int b = blockIdx.x;
    const float4* xr = (const float4*)(x + (size_t)b * DIM);
    uint2* dh = (uint2*)(g_x + (size_t)b * DIM);
    float4 v[4];
    int c0 = threadIdx.x;
    float s = 0.f;
#pragma unroll
    for (int it = 0; it < 4; ++it) v[it] = __ldg(&xr[c0 + it * 256]);
#pragma unroll
    for (int it = 0; it < 4; ++it) {
        dh[c0 + it * 256] = pk4(v[it]);
        s += v[it].x * v[it].x + v[it].y * v[it].y + v[it].z * v[it].z + v[it].w * v[it].w;
    }
    __shared__ float red[8];
#pragma unroll
    for (int o = 16; o > 0; o >>= 1) s += __shfl_down_sync(0xffffffffu, s, o);
    if ((threadIdx.x & 31) == 0) red[threadIdx.x >> 5] = s;
    __syncthreads();
    if (threadIdx.x == 0) {
        float tot = 0.f;
#pragma unroll
        for (int i = 0; i < 8; ++i) tot += red[i];
        g_norm[b] = sqrtf(tot);
    }
}

// permuted row-gather U -> Ar/Ai (fp16). (U1 conversion lives inside gemm1's grid.)
__global__ __launch_bounds__(256) void conv_uP_kernel(
        const float* __restrict__ Ure, const float* __restrict__ Uim) {
    int j = blockIdx.x;
    int src = g_perm[j];
    const float4* pr = (const float4*)(Ure + (size_t)src * DIM);
    const float4* pi = (const float4*)(Uim + (size_t)src * DIM);
    uint2* dr = (uint2*)(g_Ar + (size_t)j * DIM);
    uint2* di = (uint2*)(g_Ai + (size_t)j * DIM);
    float4 v[4], w[4];
    int c0 = threadIdx.x;
#pragma unroll
    for (int it = 0; it < 4; ++it) v[it] = __ldg(&pr[c0 + it * 256]);
#pragma unroll
    for (int it = 0; it < 4; ++it) w[it] = __ldg(&pi[c0 + it * 256]);
#pragma unroll
    for (int it = 0; it < 4; ++it) {
        int c = c0 + it * 256;
        dr[c] = pk4(v[it]);
        di[c] = pk4(w[it]);
    }
}

// ---------------------------------------------------------------------------
// GEMM1 (fp16) + fused U1 conversion (heterogeneous grid):
//   blockIdx.x <  256 : GEMM tile  s[j,b] = U·x, epilogue sr/si/sp [b][k]
//   blockIdx.x >= 256 : convert U1 row (j = bid-256) -> Br, Bi, Bp fp16
// ---------------------------------------------------------------------------
__global__ __launch_bounds__(256, 1)
void gemm1_kernel(const float* __restrict__ U1re, const float* __restrict__ U1im) {
    const int tid = threadIdx.x;

    if (blockIdx.x >= G1_TILES) {
        // ---- conv_u1 path (no smem use, no syncs) ----
        int j = blockIdx.x - G1_TILES;
        const float4* pr = (const float4*)(U1re + (size_t)j * DIM);
        const float4* pi = (const float4*)(U1im + (size_t)j * DIM);
        uint2* dr = (uint2*)(g_Br + (size_t)j * DIM);
        uint2* di = (uint2*)(g_Bi + (size_t)j * DIM);
        uint2* dp = (uint2*)(g_Bp + (size_t)j * DIM);
        float4 v[4], w[4];
#pragma unroll
        for (int it = 0; it < 4; ++it) v[it] = __ldg(&pr[tid + it * 256]);
#pragma unroll
        for (int it = 0; it < 4; ++it) w[it] = __ldg(&pi[tid + it * 256]);
#pragma unroll
        for (int it = 0; it < 4; ++it) {
            int c = tid + it * 256;
            dr[c] = pk4(v[it]);
            di[c] = pk4(w[it]);
            float4 p;
            p.x = v[it].x + w[it].x; p.y = v[it].y + w[it].y;
            p.z = v[it].z + w[it].z; p.w = v[it].w + w[it].w;
            dp[c] = pk4(p);
        }
        return;
    }

    // ---- GEMM path ----
    extern __shared__ char smem[];
    uint32_t sbase = (uint32_t)__cvta_generic_to_shared(smem);
    const int lane = tid & 31, wid = tid >> 5;
    const int g = lane >> 2, tg = lane & 3;
    const int wm0 = (wid >> 2) * 64, wn0 = (wid & 3) * 32;
    const int m0 = (blockIdx.x >> 3) * 128, n0 = (blockIdx.x & 7) * 128;

    float cr[4][4][4], ci[4][4][4];
#pragma unroll
    for (int a = 0; a < 4; ++a)
#pragma unroll
        for (int b = 0; b < 4; ++b)
#pragma unroll
            for (int c = 0; c < 4; ++c) { cr[a][b][c] = 0.f; ci[a][b][c] = 0.f; }

    uint32_t apre[4], axor[4], bpre[4], bxor[4];
#pragma unroll
    for (int mt = 0; mt < 4; ++mt) {
        int r = wm0 + mt * 16 + (lane & 15);
        apre[mt] = r * 128;
        axor[mt] = (r & 7) << 4;
    }
#pragma unroll
    for (int nt = 0; nt < 4; ++nt) {
        int r = wn0 + nt * 8 + (lane & 7);
        bpre[nt] = r * 128;
        bxor[nt] = (r & 7) << 4;
    }
    const uint32_t ahalf = (lane >> 4) << 4;
    const uint32_t bhalf = ((lane >> 3) & 1) << 4;

#define G1_LOAD(st, t) do {                                \
    uint32_t _sb = sbase + (st) * G1S; int _k0 = (t) * BK;  \
    cpah(g_Ar, m0, _k0, _sb + 0 * TS, tid);                 \
    cpah(g_Ai, m0, _k0, _sb + 1 * TS, tid);                 \
    cpah(g_x,  n0, _k0, _sb + 2 * TS, tid);                 \
} while (0)

    G1_LOAD(0, 0); CP_COMMIT();
    for (int t = 0; t < NS; ++t) {
        if (t + 1 < NS) { G1_LOAD((t + 1) & 1, t + 1); CP_COMMIT(); CP_WAIT1(); }
        else CP_WAIT0();
        __syncthreads();
        uint32_t sb = sbase + (t & 1) * G1S;
#pragma unroll
        for (int j = 0; j < 4; ++j) {                 // 4 k16 steps per k64 tile
            const uint32_t ko = j * 32;               // 16 halves = 32B
            uint32_t bv[4][2], av[4][4];
#pragma unroll
            for (int nt = 0; nt < 4; ++nt)
                ldsm2(bv[nt], sb + 2 * TS + bpre[nt] + ((ko + bhalf) ^ bxor[nt]));
#pragma unroll
            for (int mt = 0; mt < 4; ++mt)
                ldsm4(av[mt], sb + 0 * TS + apre[mt] + ((ko + ahalf) ^ axor[mt]));
            MMA_BLK(cr, av, bv);
#pragma unroll
            for (int mt = 0; mt < 4; ++mt)
                ldsm4(av[mt], sb + 1 * TS + apre[mt] + ((ko + ahalf) ^ axor[mt]));
            MMA_BLK(ci, av, bv);
        }
        __syncthreads();
    }
#undef G1_LOAD

#pragma unroll
    for (int mt = 0; mt < 4; ++mt)
#pragma unroll
        for (int nt = 0; nt < 4; ++nt)
#pragma unroll
            for (int c = 0; c < 4; ++c) {
                const int m = m0 + wm0 + mt * 16 + g + ((c >> 1) << 3);
                const int b = n0 + wn0 + nt * 8 + tg * 2 + (c & 1);
                const size_t o = (size_t)b * DIM + m;
                const float re = cr[mt][nt][c], im = ci[mt][nt][c];
                g_sr[o] = __float2half_rn(re);
                g_si[o] = __float2half_rn(im);
                g_sp[o] = __float2half_rn(re + im);
            }
}

// ---------------------------------------------------------------------------
// GEMM2 (fp16, Karatsuba 3M): T1=Br·Sr, T2=Bi·Si, T3=Bp·Sp
// re = T1-T2, im = T3-T1-T2 ; out = |.|/norm.
// smem arrays: 0 Br, 1 Bi, 2 Bp, 3 Sr, 4 Si, 5 Sp.
// ---------------------------------------------------------------------------
__global__ __launch_bounds__(256, 1) void gemm2_kernel(float* __restrict__ out) {
    extern __shared__ char smem[];
    uint32_t sbase = (uint32_t)__cvta_generic_to_shared(smem);
    const int tid = threadIdx.x, lane = tid & 31, wid = tid >> 5;
    const int g = lane >> 2, tg = lane & 3;
    const int wm0 = (wid >> 2) * 64, wn0 = (wid & 3) * 32;
    const int m0 = blockIdx.y * 128, n0 = blockIdx.x * 128;

    float acc[3][4][4][4];
#pragma unroll
    for (int p = 0; p < 3; ++p)
#pragma unroll
        for (int a = 0; a < 4; ++a)
#pragma unroll
            for (int b = 0; b < 4; ++b)
#pragma unroll
                for (int c = 0; c < 4; ++c) acc[p][a][b][c] = 0.f;

    uint32_t apre[4], axor[4], bpre[4], bxor[4];
#pragma unroll
    for (int mt = 0; mt < 4; ++mt) {
        int r = wm0 + mt * 16 + (lane & 15);
        apre[mt] = r * 128;
        axor[mt] = (r & 7) << 4;
    }
#pragma unroll
    for (int nt = 0; nt < 4; ++nt) {
        int r = wn0 + nt * 8 + (lane & 7);
        bpre[nt] = r * 128;
        bxor[nt] = (r & 7) << 4;
    }
    const uint32_t ahalf = (lane >> 4) << 4;
    const uint32_t bhalf = ((lane >> 3) & 1) << 4;

#define G2_LOAD(st, t) do {                                \
    uint32_t _sb = sbase + (st) * G2S; int _k0 = (t) * BK;  \
    cpah(g_Br, m0, _k0, _sb + 0 * TS, tid);                 \
    cpah(g_Bi, m0, _k0, _sb + 1 * TS, tid);                 \
    cpah(g_Bp, m0, _k0, _sb + 2 * TS, tid);                 \
    cpah(g_sr, n0, _k0, _sb + 3 * TS, tid);                 \
    cpah(g_si, n0, _k0, _sb + 4 * TS, tid);                 \
    cpah(g_sp, n0, _k0, _sb + 5 * TS, tid);                 \
} while (0)

    G2_LOAD(0, 0); CP_COMMIT();
    for (int t = 0; t < NS; ++t) {
        if (t + 1 < NS) { G2_LOAD((t + 1) & 1, t + 1); CP_COMMIT(); CP_WAIT1(); }
        else CP_WAIT0();
        __syncthreads();
        uint32_t sb = sbase + (t & 1) * G2S;
#pragma unroll
        for (int j = 0; j < 4; ++j) {
            const uint32_t ko = j * 32;
#pragma unroll
            for (int p = 0; p < 3; ++p) {
                uint32_t av[4][4], bv[4][2];
#pragma unroll
                for (int mt = 0; mt < 4; ++mt)
                    ldsm4(av[mt], sb + p * TS + apre[mt] + ((ko + ahalf) ^ axor[mt]));
#pragma unroll
                for (int nt = 0; nt < 4; ++nt)
                    ldsm2(bv[nt], sb + (3 + p) * TS + bpre[nt] + ((ko + bhalf) ^ bxor[nt]));
                MMA_BLK(acc[p], av, bv);
            }
        }
        __syncthreads();
    }
#undef G2_LOAD

#pragma unroll
    for (int mt = 0; mt < 4; ++mt)
#pragma unroll
        for (int nt = 0; nt < 4; ++nt)
#pragma unroll
            for (int c = 0; c < 4; ++c) {
                const int i = m0 + wm0 + mt * 16 + g + ((c >> 1) << 3);
                const int b = n0 + wn0 + nt * 8 + tg * 2 + (c & 1);
                const float t1 = acc[0][mt][nt][c];
                const float t2 = acc[1][mt][nt][c];
                const float t3 = acc[2][mt][nt][c];
                const float re = t1 - t2;
                const float im = t3 - t1 - t2;
                out[(size_t)b * DIM + i] = sqrtf(re * re + im * im) / g_norm[b];
            }
}

// ---------------------------------------------------------------------------
extern "C" void kernel_launch(void* const* d_in, const int* in_sizes, int n_in,
                              void* d_out, int out_size) {
    const float* x     = (const float*)d_in[0];
    const float* U_re  = (const float*)d_in[1];
    const float* U_im  = (const float*)d_in[2];
    const float* U1_re = (const float*)d_in[3];
    const float* U1_im = (const float*)d_in[4];
    float* out = (float*)d_out;

    cudaFuncSetAttribute(gemm1_kernel, cudaFuncAttributeMaxDynamicSharedMemorySize, 2 * G1S);
    cudaFuncSetAttribute(gemm2_kernel, cudaFuncAttributeMaxDynamicSharedMemorySize, 2 * G2S);

    perm_kernel<<<DIM / 256, 256>>>();
    normx_kernel<<<BSZ, 256>>>(x);
    conv_uP_kernel<<<DIM, 256>>>(U_re, U_im);

    // gemm1 tiles + fused U1 conversion blocks
    gemm1_kernel<<<G1_TILES + DIM, 256, 2 * G1S>>>(U1_re, U1_im);

    dim3 g2(BSZ / 128, DIM / 128);   // (8, 32)
    gemm2_kernel<<<g2, 256, 2 * G2S>>>(out);
}